// round 11
// baseline (speedup 1.0000x reference)
#include <cuda_runtime.h>
#include <math.h>

#define TOPK     64
#define NBINS    65536
#define NCHUNK   256
#define MAXCAND  4096
#define TPB      512          // 16 warps
#define NWARPS   (TPB / 32)
#define NBLOCKS  148          // 1 per SM, persistent
#define DDIM     512
#define ROWBYTES 2048         // one row = 512 floats
#define RSTAGES  5            // per-warp pipeline depth

__device__ float        g_alpha[262144];
__device__ unsigned int g_hist[NBINS];     // fkey >> 16 (fine hist only)
__device__ unsigned int g_done;            // zero-init; reset each run

__device__ __forceinline__ unsigned int fkey(float f) {
    unsigned int b = __float_as_uint(f);
    return (b & 0x80000000u) ? ~b : (b | 0x80000000u);
}

__device__ __forceinline__ unsigned int smem_u32(const void* p) {
    return (unsigned int)__cvta_generic_to_shared(p);
}
__device__ __forceinline__ void mbar_init(unsigned int mbar, unsigned int count) {
    asm volatile("mbarrier.init.shared.b64 [%0], %1;" :: "r"(mbar), "r"(count) : "memory");
}
__device__ __forceinline__ void mbar_expect_tx(unsigned int mbar, unsigned int bytes) {
    asm volatile("mbarrier.arrive.expect_tx.shared.b64 _, [%0], %1;"
                 :: "r"(mbar), "r"(bytes) : "memory");
}
__device__ __forceinline__ void tma_bulk_1d(unsigned int dst_smem, const void* src,
                                            unsigned int bytes, unsigned int mbar) {
    asm volatile("cp.async.bulk.shared::cta.global.mbarrier::complete_tx::bytes "
                 "[%0], [%1], %2, [%3];"
                 :: "r"(dst_smem), "l"(src), "r"(bytes), "r"(mbar) : "memory");
}
__device__ __forceinline__ void mbar_wait(unsigned int mbar, unsigned int parity) {
    unsigned int done;
    asm volatile("{\n\t.reg .pred p;\n\t"
                 "mbarrier.try_wait.parity.acquire.cta.shared::cta.b64 p, [%1], %2;\n\t"
                 "selp.b32 %0, 1, 0, p;\n\t}"
                 : "=r"(done) : "r"(mbar), "r"(parity) : "memory");
    if (!done) {
        asm volatile("{\n\t.reg .pred P1;\n\t"
                     "WL_%=:\n\t"
                     "mbarrier.try_wait.parity.acquire.cta.shared::cta.b64 P1, [%0], %1, 0x989680;\n\t"
                     "@P1 bra.uni WD_%=;\n\t"
                     "bra.uni WL_%=;\n\t"
                     "WD_%=:\n\t}"
                     :: "r"(mbar), "r"(parity) : "memory");
    }
}

// dynamic smem layout:
//   [0, 2048)    sv (512 floats)
//   [2048, 2688) mbarriers: NWARPS * RSTAGES * 8 bytes = 640
//   [4096, ...)  per-warp row buffers: NWARPS * RSTAGES * ROWBYTES = 160 KB
#define BUF_OFF    4096
#define SMEM_BYTES (BUF_OFF + NWARPS * RSTAGES * ROWBYTES)

__global__ void __launch_bounds__(TPB, 1)
fused_kernel(const float* __restrict__ v,
             const float* __restrict__ vs,
             const float* __restrict__ scores,
             float* __restrict__ out, int N) {
    extern __shared__ char smem_raw[];
    float* sv = (float*)smem_raw;
    unsigned long long* mbars = (unsigned long long*)(smem_raw + 2048);
    float* buf = (float*)(smem_raw + BUF_OFF);

    const int tid  = threadIdx.x;
    const int lane = tid & 31;
    const int warp = tid >> 5;

    for (int i = tid; i < DDIM; i += TPB) sv[i] = v[i];
    if (tid < NWARPS * RSTAGES)
        mbar_init(smem_u32(&mbars[tid]), 1);
    __syncthreads();

    const unsigned int mb0 = smem_u32(&mbars[warp * RSTAGES]);
    float* wbuf = buf + warp * (RSTAGES * (ROWBYTES / 4));

    // v slice held in registers for the whole matvec
    const float4* vv4 = (const float4*)sv;
    const float4 y0 = vv4[lane +  0];
    const float4 y1 = vv4[lane + 32];
    const float4 y2 = vv4[lane + 64];
    const float4 y3 = vv4[lane + 96];

    const int gwarp  = blockIdx.x * NWARPS + warp;
    const int nwarps = NBLOCKS * NWARPS;

    // lane 0 issues a 2 KB one-row TMA into stage j % RSTAGES
    auto issue_row = [&](int j) {
        int row = gwarp + j * nwarps;
        if (row < N && lane == 0) {
            int s = j % RSTAGES;
            unsigned int mb = mb0 + 8u * s;
            mbar_expect_tx(mb, ROWBYTES);
            tma_bulk_1d(smem_u32(wbuf + s * (ROWBYTES / 4)),
                        vs + (size_t)row * DDIM, ROWBYTES, mb);
        }
    };

#pragma unroll
    for (int j = 0; j < RSTAGES; j++) issue_row(j);

    // ---------------- phase 1: per-warp decoupled matvec ---------------------
    for (int j = 0; ; j++) {
        int row = gwarp + j * nwarps;
        if (row >= N) break;
        int s = j % RSTAGES;
        mbar_wait(mb0 + 8u * s, (unsigned int)((j / RSTAGES) & 1));

        const float4* bb = (const float4*)(wbuf + s * (ROWBYTES / 4));
        float4 x0 = bb[lane +  0];
        float4 x1 = bb[lane + 32];
        float4 x2 = bb[lane + 64];
        float4 x3 = bb[lane + 96];
        float a0 = x0.x*y0.x + x0.y*y0.y + x0.z*y0.z + x0.w*y0.w;
        float a1 = x1.x*y1.x + x1.y*y1.y + x1.z*y1.z + x1.w*y1.w;
        float a2 = x2.x*y2.x + x2.y*y2.y + x2.z*y2.z + x2.w*y2.w;
        float a3 = x3.x*y3.x + x3.y*y3.y + x3.z*y3.z + x3.w*y3.w;
        float acc = (a0 + a1) + (a2 + a3);
#pragma unroll
        for (int o = 16; o; o >>= 1) acc += __shfl_xor_sync(0xffffffffu, acc, o);

        // all lanes are past their smem reads (shuffles synchronized the warp):
        // stage s is reusable; lane 0 refills it and writes the result
        if (lane == 0) {
            g_alpha[row] = acc;
            atomicAdd(&g_hist[fkey(acc) >> 16], 1u);
        }
        issue_row(j + RSTAGES);
    }

    // ---------------- last-block election ------------------------------------
    __shared__ unsigned int s_isLast;
    __threadfence();
    __syncthreads();
    if (tid == 0)
        s_isLast = (atomicAdd(&g_done, 1u) == gridDim.x - 1) ? 1u : 0u;
    __syncthreads();
    if (!s_isLast) return;
    __threadfence();

    // -------- phase 2: coarse sums from fine hist, then threshold bin --------
    __shared__ unsigned int sc[NCHUNK];
    {
        const uint4* h4 = (const uint4*)g_hist;
        unsigned int s = 0;
        int base = tid * 32;                      // 128 bins per thread
#pragma unroll 8
        for (int j = 0; j < 32; j++) {
            uint4 u = h4[base + j];
            s += u.x + u.y + u.z + u.w;
        }
        __shared__ unsigned int half[TPB];
        half[tid] = s;
        __syncthreads();
        if (tid < NCHUNK) sc[tid] = half[2 * tid] + half[2 * tid + 1];
        __syncthreads();
    }

    __shared__ int s_chunk;
    __shared__ unsigned int s_above;
    __shared__ unsigned int s_tb;
    if (tid == 0) {
        unsigned int cum = 0;
        int c;
        for (c = 255; c >= 0; c--) {
            if (cum + sc[c] >= (unsigned int)TOPK) break;
            cum += sc[c];
        }
        if (c < 0) c = 0;
        s_chunk = c;
        s_above = cum;
    }
    __syncthreads();
    __shared__ unsigned int sf[256];
    if (tid < 256) sf[tid] = g_hist[s_chunk * 256 + tid];
    __syncthreads();
    if (tid == 0) {
        unsigned int cum = s_above;
        int b;
        for (b = 255; b >= 0; b--) {
            cum += sf[b];
            if (cum >= (unsigned int)TOPK) break;
        }
        if (b < 0) b = 0;
        s_tb = (unsigned int)(s_chunk * 256 + b);
    }
    __syncthreads();
    unsigned int tb = s_tb;

    // -------- phase 3: scan alpha (L2-hot), candidates into smem -------------
    float* sval = buf;                      // alias row buffers
    int*   sidx = (int*)(buf + MAXCAND);
    __shared__ int s_cand;
    if (tid == 0) s_cand = 0;
    __syncthreads();

    int n4 = N >> 2;
    for (int i = tid; i < n4; i += TPB) {
        float4 a = ((const float4*)g_alpha)[i];
        int base = i << 2;
        if ((fkey(a.x) >> 16) >= tb) {
            int p = atomicAdd(&s_cand, 1);
            if (p < MAXCAND) { sval[p] = a.x; sidx[p] = base + 0; }
        }
        if ((fkey(a.y) >> 16) >= tb) {
            int p = atomicAdd(&s_cand, 1);
            if (p < MAXCAND) { sval[p] = a.y; sidx[p] = base + 1; }
        }
        if ((fkey(a.z) >> 16) >= tb) {
            int p = atomicAdd(&s_cand, 1);
            if (p < MAXCAND) { sval[p] = a.z; sidx[p] = base + 2; }
        }
        if ((fkey(a.w) >> 16) >= tb) {
            int p = atomicAdd(&s_cand, 1);
            if (p < MAXCAND) { sval[p] = a.w; sidx[p] = base + 3; }
        }
    }
    if (tid == 0) {
        for (int i = n4 << 2; i < N; i++) {
            float a = g_alpha[i];
            if ((fkey(a) >> 16) >= tb) {
                int p = atomicAdd(&s_cand, 1);
                if (p < MAXCAND) { sval[p] = a; sidx[p] = i; }
            }
        }
    }
    __syncthreads();
    int C = s_cand;
    if (C > MAXCAND) C = MAXCAND;

    // -------- phase 4: max, rank-select, softmax, weighted sum ---------------
    __shared__ float r1[TPB];
    __shared__ float r2[TPB];

    float m = -INFINITY;
    for (int i = tid; i < C; i += TPB) m = fmaxf(m, sval[i]);
    r1[tid] = m;
    __syncthreads();
    for (int s = TPB / 2; s; s >>= 1) {
        if (tid < s) r1[tid] = fmaxf(r1[tid], r1[tid + s]);
        __syncthreads();
    }
    m = r1[0];
    __syncthreads();

    float se = 0.f, acc = 0.f;
    for (int i = tid; i < C; i += TPB) {
        float vi = sval[i];
        unsigned int ki = fkey(vi);
        int rank = 0;
        for (int j = 0; j < C; j++) {
            unsigned int kj = fkey(sval[j]);
            rank += (kj > ki) || (kj == ki && j < i);
        }
        if (rank < TOPK) {
            float e = __expf(vi - m);
            se += e;
            acc += e * scores[sidx[i]];
        }
    }
    r1[tid] = se;
    r2[tid] = acc;
    __syncthreads();
    for (int s = TPB / 2; s; s >>= 1) {
        if (tid < s) {
            r1[tid] += r1[tid + s];
            r2[tid] += r2[tid + s];
        }
        __syncthreads();
    }
    if (tid == 0) out[0] = r2[0] / r1[0];

    // -------- phase 5: selective reset for next graph replay -----------------
    if (tid < NCHUNK) {
        if (sc[tid] != 0u) {
            uint4 z = make_uint4(0u, 0u, 0u, 0u);
            uint4* dst = (uint4*)&g_hist[tid * 256];
#pragma unroll
            for (int j = 0; j < 64; j++) dst[j] = z;
        }
    }
    if (tid == 0) g_done = 0u;
}

// ---------------- launch ------------------------------------------------------
extern "C" void kernel_launch(void* const* d_in, const int* in_sizes, int n_in,
                              void* d_out, int out_size) {
    const float* v      = (const float*)d_in[0];
    const float* vs     = (const float*)d_in[1];
    const float* scores = (const float*)d_in[2];
    float* out = (float*)d_out;
    int N = in_sizes[2];
    (void)n_in; (void)out_size;

    cudaFuncSetAttribute(fused_kernel,
                         cudaFuncAttributeMaxDynamicSharedMemorySize, SMEM_BYTES);
    fused_kernel<<<NBLOCKS, TPB, SMEM_BYTES>>>(v, vs, scores, out, N);
}

// round 12
// speedup vs baseline: 1.5223x; 1.5223x over previous
#include <cuda_runtime.h>
#include <math.h>

#define TOPK     64
#define TPB      256
#define BPSM     6
#define NBLOCKS  (148 * BPSM)     // 888 persistent blocks, one wave
#define DDIM     512
#define MAXC_G   8192             // global candidate buffer
#define MAXFILT  512              // filtered candidates (smem)
#define NHBINS   1024
#define SIG_MULT 2.5f

__device__ float        g_alpha[262144];
__device__ float        g_cval[MAXC_G];
__device__ int          g_cidx[MAXC_G];
__device__ int          g_ccount;          // zero-init; reset each run
__device__ unsigned int g_done;            // zero-init; reset each run

// order-preserving float -> uint key
__device__ __forceinline__ unsigned int fkey(float f) {
    unsigned int b = __float_as_uint(f);
    return (b & 0x80000000u) ? ~b : (b | 0x80000000u);
}

__global__ void __launch_bounds__(TPB, BPSM)
fused_kernel(const float* __restrict__ v,
             const float* __restrict__ vs,
             const float* __restrict__ scores,
             float* __restrict__ out, int N) {
    __shared__ float        sv[DDIM];
    __shared__ unsigned int hist[NHBINS];
    __shared__ unsigned int part[TPB];
    __shared__ float        fval[MAXFILT];
    __shared__ int          fidx[MAXFILT];
    __shared__ float        r1[TPB];
    __shared__ float        r2[TPB];
    __shared__ int          ri[TPB];
    __shared__ float        topv[TOPK];
    __shared__ int          topi[TOPK];

    const int tid  = threadIdx.x;
    const int lane = tid & 31;
    const int warp = tid >> 5;

    for (int i = tid; i < DDIM; i += TPB) sv[i] = v[i];
    __syncthreads();

    const float4* vv4 = (const float4*)sv;

    // analytic candidate threshold: alpha ~ N(0, ||v||^2)
    float vn;
    {
        float4 a = vv4[lane], b = vv4[lane + 32], c = vv4[lane + 64], d = vv4[lane + 96];
        vn = a.x*a.x + a.y*a.y + a.z*a.z + a.w*a.w
           + b.x*b.x + b.y*b.y + b.z*b.z + b.w*b.w
           + c.x*c.x + c.y*c.y + c.z*c.z + c.w*c.w
           + d.x*d.x + d.y*d.y + d.z*d.z + d.w*d.w;
#pragma unroll
        for (int o = 16; o; o >>= 1) vn += __shfl_xor_sync(0xffffffffu, vn, o);
    }
    const float thr = SIG_MULT * sqrtf(vn);

    const int gwarp = blockIdx.x * (TPB / 32) + warp;
    const int nw    = NBLOCKS * (TPB / 32);

    // ---------------- phase 1: matvec + threshold append ---------------------
    for (int row = gwarp; row < N; row += nw) {
        const float4* p = (const float4*)(vs + (size_t)row * DDIM);
        float4 x0 = p[lane +  0];
        float4 x1 = p[lane + 32];
        float4 x2 = p[lane + 64];
        float4 x3 = p[lane + 96];
        float4 yy0 = vv4[lane +  0];
        float4 yy1 = vv4[lane + 32];
        float4 yy2 = vv4[lane + 64];
        float4 yy3 = vv4[lane + 96];
        float a0 = x0.x*yy0.x + x0.y*yy0.y + x0.z*yy0.z + x0.w*yy0.w;
        float a1 = x1.x*yy1.x + x1.y*yy1.y + x1.z*yy1.z + x1.w*yy1.w;
        float a2 = x2.x*yy2.x + x2.y*yy2.y + x2.z*yy2.z + x2.w*yy2.w;
        float a3 = x3.x*yy3.x + x3.y*yy3.y + x3.z*yy3.z + x3.w*yy3.w;
        float acc = (a0 + a1) + (a2 + a3);
#pragma unroll
        for (int o = 16; o; o >>= 1) acc += __shfl_xor_sync(0xffffffffu, acc, o);
        if (lane == 0) {
            g_alpha[row] = acc;
            if (acc > thr) {
                int q = atomicAdd(&g_ccount, 1);
                if (q < MAXC_G) { g_cval[q] = acc; g_cidx[q] = row; }
            }
        }
    }

    // ---------------- last-block election ------------------------------------
    __shared__ unsigned int s_isLast;
    __threadfence();
    __syncthreads();
    if (tid == 0)
        s_isLast = (atomicAdd(&g_done, 1u) == NBLOCKS - 1) ? 1u : 0u;
    __syncthreads();
    if (!s_isLast) return;
    __threadfence();

    // ---------------- tail: exact top-K from candidates ----------------------
    int C = g_ccount;
    __shared__ int s_fail;
    if (tid == 0) s_fail = (C < TOPK || C > MAXC_G) ? 1 : 0;
    __syncthreads();

    int F = 0;
    if (!s_fail) {
        // histogram candidate keys (narrow range above thr) into 1024 bins
        for (int i = tid; i < NHBINS; i += TPB) hist[i] = 0u;
        __syncthreads();
        unsigned int base = fkey(thr) >> 16;
        for (int i = tid; i < C; i += TPB) {
            unsigned int b = (fkey(g_cval[i]) >> 16) - base;
            if (b > NHBINS - 1) b = NHBINS - 1;
            atomicAdd(&hist[b], 1u);
        }
        __syncthreads();
        // suffix search for threshold bin
        part[tid] = hist[4*tid] + hist[4*tid+1] + hist[4*tid+2] + hist[4*tid+3];
        __syncthreads();
        __shared__ int s_bstar;
        if (tid == 0) {
            unsigned int cum = 0;
            int g;
            for (g = TPB - 1; g >= 0; g--) {
                if (cum + part[g] >= (unsigned int)TOPK) break;
                cum += part[g];
            }
            if (g < 0) g = 0;
            int b;
            for (b = 4*g + 3; b > 4*g; b--) {
                if (cum + hist[b] >= (unsigned int)TOPK) break;
                cum += hist[b];
            }
            s_bstar = b;
        }
        __syncthreads();
        int bstar = s_bstar;
        // gather candidates with bin >= bstar into smem
        __shared__ int s_nf;
        if (tid == 0) s_nf = 0;
        __syncthreads();
        for (int i = tid; i < C; i += TPB) {
            float val = g_cval[i];
            unsigned int b = (fkey(val) >> 16) - base;
            if (b > NHBINS - 1) b = NHBINS - 1;
            if ((int)b >= bstar) {
                int q = atomicAdd(&s_nf, 1);
                if (q < MAXFILT) { fval[q] = val; fidx[q] = g_cidx[i]; }
            }
        }
        __syncthreads();
        F = s_nf;
        if (tid == 0 && (F > MAXFILT || F < TOPK)) s_fail = 1;
        __syncthreads();
    }

    if (!s_fail) {
        // exact rank-select + softmax + weighted sum over F (~64..200) entries
        float m = -INFINITY;
        for (int i = tid; i < F; i += TPB) m = fmaxf(m, fval[i]);
        r1[tid] = m;
        __syncthreads();
        for (int s = TPB / 2; s; s >>= 1) {
            if (tid < s) r1[tid] = fmaxf(r1[tid], r1[tid + s]);
            __syncthreads();
        }
        m = r1[0];
        __syncthreads();

        float se = 0.f, acc = 0.f;
        for (int i = tid; i < F; i += TPB) {
            float vi = fval[i];
            unsigned int ki = fkey(vi);
            int ii = fidx[i];
            int rank = 0;
            for (int j = 0; j < F; j++) {
                unsigned int kj = fkey(fval[j]);
                rank += (kj > ki) || (kj == ki && fidx[j] < ii);
            }
            if (rank < TOPK) {
                float e = __expf(vi - m);
                se += e;
                acc += e * scores[ii];
            }
        }
        r1[tid] = se;
        r2[tid] = acc;
        __syncthreads();
        for (int s = TPB / 2; s; s >>= 1) {
            if (tid < s) { r1[tid] += r1[tid + s]; r2[tid] += r2[tid + s]; }
            __syncthreads();
        }
        if (tid == 0) out[0] = r2[0] / r1[0];
    } else {
        // robust fallback: 64 exact argmax passes over g_alpha (never on bench data)
        for (int k = 0; k < TOPK; k++) {
            float best = -INFINITY; int bi = 0x7fffffff;
            for (int i = tid; i < N; i += TPB) {
                float a = g_alpha[i];
                if (a > best || (a == best && i < bi)) { best = a; bi = i; }
            }
            r1[tid] = best; ri[tid] = bi;
            __syncthreads();
            for (int s = TPB / 2; s; s >>= 1) {
                if (tid < s) {
                    float ov = r1[tid + s]; int oi = ri[tid + s];
                    if (ov > r1[tid] || (ov == r1[tid] && oi < ri[tid])) {
                        r1[tid] = ov; ri[tid] = oi;
                    }
                }
                __syncthreads();
            }
            if (tid == 0) {
                topv[k] = r1[0]; topi[k] = ri[0];
                g_alpha[ri[0]] = -INFINITY;
            }
            __syncthreads();
        }
        if (tid == 0) {
            float m = topv[0];
            float se = 0.f, acc = 0.f;
            for (int k = 0; k < TOPK; k++) {
                float e = __expf(topv[k] - m);
                se += e;
                acc += e * scores[topi[k]];
            }
            out[0] = acc / se;
        }
    }

    // reset for next graph replay
    if (tid == 0) { g_ccount = 0; g_done = 0u; }
}

// ---------------- launch ------------------------------------------------------
extern "C" void kernel_launch(void* const* d_in, const int* in_sizes, int n_in,
                              void* d_out, int out_size) {
    const float* v      = (const float*)d_in[0];
    const float* vs     = (const float*)d_in[1];
    const float* scores = (const float*)d_in[2];
    float* out = (float*)d_out;
    int N = in_sizes[2];
    (void)n_in; (void)out_size;

    fused_kernel<<<NBLOCKS, TPB>>>(v, vs, scores, out, N);
}